// round 3
// baseline (speedup 1.0000x reference)
#include <cuda_runtime.h>
#include <stdint.h>

#define OUTF 8192
#define INF  8192
#define BATCH 32

typedef unsigned long long u64;

// 256MB dense scratch for the materialized weight matrix (row-major [OUTF][INF]).
__device__ float g_W[(size_t)OUTF * (size_t)INF];

// ---------------------------------------------------------------------------
// Bucketing: COO entries are compacted per (slice, warp) into fixed-stride
// regions so the per-slice scatter only reads its own slice's records and
// the allocation needs no atomics (each warp owns its region).
// ---------------------------------------------------------------------------
#define NSLICE 3
#define SLICE_ROWS 2731          // ceil(8192/3); slice = ~87MB < 126MB L2
#define NW 8192                  // total warps in bucket pass
#define WSTRIDE 4608             // region stride per (slice, warp), entries

__device__ u64 g_buckets[(size_t)NSLICE * NW * WSTRIDE];   // ~906MB scratch
__device__ int g_counts[NSLICE * NW];

__global__ __launch_bounds__(256)
void bucket_kernel(const float* __restrict__ vals,
                   const int* __restrict__ rows,
                   const int* __restrict__ cols,
                   int nnz, int wchunk) {
    const int gw   = (blockIdx.x * blockDim.x + threadIdx.x) >> 5;  // 0..NW-1
    const int lane = threadIdx.x & 31;
    const unsigned lt = (1u << lane) - 1u;

    int start = gw * wchunk;
    int end   = start + wchunk;
    if (end > nnz) end = nnz;

    u64* r0 = g_buckets + ((size_t)(0 * NW + gw)) * WSTRIDE;
    u64* r1 = g_buckets + ((size_t)(1 * NW + gw)) * WSTRIDE;
    u64* r2 = g_buckets + ((size_t)(2 * NW + gw)) * WSTRIDE;
    int c0 = 0, c1 = 0, c2 = 0;

    for (int base = start; base < end; base += 32) {
        int i = base + lane;
        bool valid = i < end;
        int   r = valid ? __ldcs(rows + i) : -1;
        int   c = valid ? __ldcs(cols + i) : 0;
        float v = valid ? __ldcs(vals + i) : 0.f;

        int s  = (r < SLICE_ROWS) ? 0 : (r < 2 * SLICE_ROWS ? 1 : 2);
        int lo = s * SLICE_ROWS;
        unsigned key = (unsigned)(r - lo) * (unsigned)INF + (unsigned)c;
        u64 packed = (u64)key | ((u64)__float_as_uint(v) << 32);

        unsigned m0 = __ballot_sync(0xFFFFFFFFu, valid && s == 0);
        unsigned m1 = __ballot_sync(0xFFFFFFFFu, valid && s == 1);
        unsigned m2 = __ballot_sync(0xFFFFFFFFu, valid && s == 2);
        if (valid) {
            if (s == 0)      r0[c0 + __popc(m0 & lt)] = packed;
            else if (s == 1) r1[c1 + __popc(m1 & lt)] = packed;
            else             r2[c2 + __popc(m2 & lt)] = packed;
        }
        c0 += __popc(m0);
        c1 += __popc(m1);
        c2 += __popc(m2);
    }

    if (lane == 0) {
        g_counts[0 * NW + gw] = c0;
        g_counts[1 * NW + gw] = c1;
        g_counts[2 * NW + gw] = c2;
    }
}

// ---------------------------------------------------------------------------
// Zero a row-slice of W (leaves the slice dirty-resident in L2).
// ---------------------------------------------------------------------------
__global__ void zero_slice_kernel(int lo, int hi) {
    size_t n4 = (size_t)(hi - lo) * INF / 4;
    float4* p = reinterpret_cast<float4*>(g_W + (size_t)lo * INF);
    const float4 z = make_float4(0.f, 0.f, 0.f, 0.f);
    size_t stride = (size_t)gridDim.x * blockDim.x;
    for (size_t i = (size_t)blockIdx.x * blockDim.x + threadIdx.x; i < n4; i += stride)
        p[i] = z;
}

// ---------------------------------------------------------------------------
// Scatter one slice's bucketed records into the L2-resident slice.
// Records are read evict-first so they don't evict the slice.
// ---------------------------------------------------------------------------
__global__ __launch_bounds__(256)
void scatter_bucket_kernel(int s, int lo) {
    const int gw   = (blockIdx.x * blockDim.x + threadIdx.x) >> 5;
    const int lane = threadIdx.x & 31;
    const int cnt  = g_counts[s * NW + gw];
    const u64* reg = g_buckets + ((size_t)(s * NW + gw)) * WSTRIDE;
    float* Ws = g_W + (size_t)lo * INF;
    for (int j = lane; j < cnt; j += 32) {
        u64 e = __ldcs(reg + j);
        unsigned key = (unsigned)e;
        float v = __uint_as_float((unsigned)(e >> 32));
        atomicAdd(Ws + key, v);
    }
}

// ---------------------------------------------------------------------------
// out[b, o] = bias[o]   (GEMM epilogue accumulates on top via atomicAdd)
// ---------------------------------------------------------------------------
__global__ void init_out_kernel(const float* __restrict__ bias,
                                float* __restrict__ out) {
    const int n4 = (BATCH * OUTF) / 4;
    const float4* b4 = reinterpret_cast<const float4*>(bias);
    float4* o4 = reinterpret_cast<float4*>(out);
    int stride = gridDim.x * blockDim.x;
    for (int i = blockIdx.x * blockDim.x + threadIdx.x; i < n4; i += stride) {
        int o = i & (OUTF / 4 - 1);
        o4[i] = b4[o];
    }
}

// ---------------------------------------------------------------------------
// Dense GEMM  out[b,o] += sum_k in[b,k] * W[o,k]
// Block: 128 threads, C-tile 32(b) x 256(o), thread-tile 8(b) x 8(o).
// fma.rn.f32x2 packs 2 FMAs/inst. KSPLIT=8 -> 256 blocks, 2 blocks/SM.
// ---------------------------------------------------------------------------
#define OTILE 256
#define KC 16
#define KSPLIT 8
#define BS_STRIDE 260
#define AS_STRIDE 36

__device__ __forceinline__ u64 pack2(float lo, float hi) {
    u64 r; asm("mov.b64 %0, {%1, %2};" : "=l"(r) : "f"(lo), "f"(hi)); return r;
}
__device__ __forceinline__ void unpack2(u64 v, float& lo, float& hi) {
    asm("mov.b64 {%0, %1}, %2;" : "=f"(lo), "=f"(hi) : "l"(v));
}
__device__ __forceinline__ u64 fma2(u64 a, u64 b, u64 c) {
    u64 d; asm("fma.rn.f32x2 %0, %1, %2, %3;" : "=l"(d) : "l"(a), "l"(b), "l"(c));
    return d;
}

__global__ __launch_bounds__(128, 2)
void gemm_kernel(const float* __restrict__ in, float* __restrict__ out) {
    __shared__ float As[KC][AS_STRIDE];
    __shared__ float Bs[KC][BS_STRIDE];

    const int tid = threadIdx.x;
    const int ob  = blockIdx.x * OTILE;
    const int k0  = blockIdx.y * (INF / KSPLIT);
    const int NT  = (INF / KSPLIT) / KC;   // 64 tiles

    const int lb = tid >> 2;
    const int lk = (tid & 3) << 2;
    const int oq = tid & 31;
    const int bq = tid >> 5;
    const int o0 = oq * 4;
    const int b0 = bq * 8;

    u64 acc[8][4];
#pragma unroll
    for (int i = 0; i < 8; i++)
#pragma unroll
        for (int p = 0; p < 4; p++) acc[i][p] = 0ull;

    const float* aP = in + (size_t)lb * INF + k0 + lk;

    float4 pa, pb[8];
    pa = *reinterpret_cast<const float4*>(aP);
#pragma unroll
    for (int j = 0; j < 8; j++) {
        int r = j * 128 + tid;
        int o = r >> 2, k4 = (r & 3) << 2;
        pb[j] = *reinterpret_cast<const float4*>(g_W + (size_t)(ob + o) * INF + k0 + k4);
    }

    for (int t = 0; t < NT; t++) {
        As[lk + 0][lb] = pa.x;
        As[lk + 1][lb] = pa.y;
        As[lk + 2][lb] = pa.z;
        As[lk + 3][lb] = pa.w;
#pragma unroll
        for (int j = 0; j < 8; j++) {
            int r = j * 128 + tid;
            int o = r >> 2, k4 = (r & 3) << 2;
            Bs[k4 + 0][o] = pb[j].x;
            Bs[k4 + 1][o] = pb[j].y;
            Bs[k4 + 2][o] = pb[j].z;
            Bs[k4 + 3][o] = pb[j].w;
        }
        __syncthreads();

        if (t + 1 < NT) {
            const int kt = k0 + (t + 1) * KC;
            pa = *reinterpret_cast<const float4*>(aP + (size_t)(t + 1) * KC);
#pragma unroll
            for (int j = 0; j < 8; j++) {
                int r = j * 128 + tid;
                int o = r >> 2, k4 = (r & 3) << 2;
                pb[j] = *reinterpret_cast<const float4*>(g_W + (size_t)(ob + o) * INF + kt + k4);
            }
        }

#pragma unroll
        for (int kk = 0; kk < KC; kk++) {
            float4 a0 = *reinterpret_cast<const float4*>(&As[kk][b0]);
            float4 a1 = *reinterpret_cast<const float4*>(&As[kk][b0 + 4]);
            float4 w0 = *reinterpret_cast<const float4*>(&Bs[kk][o0]);
            float4 w1 = *reinterpret_cast<const float4*>(&Bs[kk][o0 + 128]);
            u64 bp[4];
            bp[0] = pack2(w0.x, w0.y);
            bp[1] = pack2(w0.z, w0.w);
            bp[2] = pack2(w1.x, w1.y);
            bp[3] = pack2(w1.z, w1.w);
            float av[8] = {a0.x, a0.y, a0.z, a0.w, a1.x, a1.y, a1.z, a1.w};
#pragma unroll
            for (int i = 0; i < 8; i++) {
                u64 aa = pack2(av[i], av[i]);
#pragma unroll
                for (int p = 0; p < 4; p++)
                    acc[i][p] = fma2(aa, bp[p], acc[i][p]);
            }
        }
        __syncthreads();
    }

    const int ocol[4] = {o0, o0 + 2, o0 + 128, o0 + 130};
#pragma unroll
    for (int i = 0; i < 8; i++) {
        float* orow = out + (size_t)(b0 + i) * OUTF + ob;
#pragma unroll
        for (int p = 0; p < 4; p++) {
            float lo, hi;
            unpack2(acc[i][p], lo, hi);
            atomicAdd(orow + ocol[p] + 0, lo);
            atomicAdd(orow + ocol[p] + 1, hi);
        }
    }
}

// ---------------------------------------------------------------------------
// launch: bucket COO -> per slice { zero -> scatter } -> init out -> GEMM
// ---------------------------------------------------------------------------
extern "C" void kernel_launch(void* const* d_in, const int* in_sizes, int n_in,
                              void* d_out, int out_size) {
    const float* in_values = (const float*)d_in[0];
    const float* values    = (const float*)d_in[1];
    const int*   indices   = (const int*)d_in[2];
    const float* bias      = (const float*)d_in[3];
    float*       out       = (float*)d_out;

    const int nnz  = in_sizes[1];
    const int* rows = indices;
    const int* cols = indices + nnz;

    int wchunk = (nnz + NW - 1) / NW;          // 4096 for NNZ=33.5M
    if (wchunk > WSTRIDE) wchunk = WSTRIDE;    // safety (cannot happen here)

    bucket_kernel<<<NW / 8, 256>>>(values, rows, cols, nnz, wchunk);

    for (int s = 0; s < NSLICE; s++) {
        int lo = s * SLICE_ROWS;
        int hi = lo + SLICE_ROWS;
        if (hi > OUTF) hi = OUTF;
        zero_slice_kernel<<<2048, 256>>>(lo, hi);
        scatter_bucket_kernel<<<NW / 8, 256>>>(s, lo);
    }

    init_out_kernel<<<256, 256>>>(bias, out);
    dim3 ggrid(OUTF / OTILE, KSPLIT);
    gemm_kernel<<<ggrid, 128>>>(in_values, out);
}